// round 15
// baseline (speedup 1.0000x reference)
#include <cuda_runtime.h>
#include <cuda_fp16.h>
#include <cstdint>

#define NF       40960
#define MDIM     256
#define NB       2048
#define ROWS     (2*NB)          // 4096 feature rows (white then black)
#define CHUNK_V4 1280            // float4s per warp chunk (NF/4/8)
#define NSEG     8               // segments per row (one per eighth)
#define SEG_CAP  32              // capacity per segment

#define TR_X      (NF/32)        // 1280
#define TR_Y      (MDIM/32)      // 8
#define TR_CTAS   (TR_X*TR_Y)    // 10240
#define SCAN_CTAS ROWS           // 4096 (one CTA per row, 8 warps = 8 eighths)
#define GATHER_CTAS NB           // 2048
#define TOTAL_CTAS (TR_CTAS + SCAN_CTAS + GATHER_CTAS)

// fp16 transposed feature-transformer weights: ft_wT[f][m], 21 MB
__device__ __half g_ftwT[NF * MDIM];
// Per-(row, eighth) compact feature-index lists + counts
__device__ int g_list[ROWS * NSEG * SEG_CAP];   // 4 MB
__device__ int g_scnt[ROWS * NSEG];
// Dependency tracking (monotonic across graph replays; never reset)
__device__ int        g_epoch;            // bumped once per launch
__device__ long long  g_trdone;           // transpose CTAs completed (cumulative)
__device__ int        g_rowflag[ROWS];    // epoch at which row's lists are ready

__global__ void bump_epoch_kernel() {
    if (threadIdx.x == 0) g_epoch = g_epoch + 1;
}

__device__ __forceinline__ float clamp01(float x) {
    return fminf(fmaxf(x, 0.0f), 1.0f);
}

__device__ __forceinline__ float4 ld_row4h(int f, int m4) {
    const uint2 u = reinterpret_cast<const uint2*>(g_ftwT + (size_t)f * MDIM)[m4];
    const __half2 h0 = *reinterpret_cast<const __half2*>(&u.x);
    const __half2 h1 = *reinterpret_cast<const __half2*>(&u.y);
    const float2 f0 = __half22float2(h0);
    const float2 f1 = __half22float2(h1);
    return make_float4(f0.x, f0.y, f1.x, f1.y);
}

// ---------------------------------------------------------------------------
// Mega-kernel: [transpose | scan | gather] with per-row flag dependencies.
// ---------------------------------------------------------------------------
__global__ __launch_bounds__(256) void nnue_mega_kernel(
    const float* __restrict__ wf,
    const float* __restrict__ bfeat,
    const float* __restrict__ ft_w,
    const float* __restrict__ stm,
    const float* __restrict__ ft_b,
    const float* __restrict__ l1_w,
    const float* __restrict__ l1_b,
    const float* __restrict__ l2_w,
    const float* __restrict__ l2_b,
    const float* __restrict__ l3_w,
    const float* __restrict__ l3_b,
    float* __restrict__ out)
{
    // shared declarations (union of branch needs; ~21KB)
    __shared__ float tile[32][33];
    __shared__ __align__(16) float s_h[512];
    __shared__ __align__(16) float s_pW[4 * 256];
    __shared__ __align__(16) float s_pB[4 * 256];
    __shared__ __align__(16) int   s_idxW[NSEG * SEG_CAP];
    __shared__ __align__(16) int   s_idxB[NSEG * SEG_CAP];
    __shared__ float s_l2w[32 * 33];
    __shared__ float s_l2x[32];
    __shared__ int   s_cntW[8], s_cntB[8];
    __shared__ int   s_nW, s_nB;

    const int tid  = threadIdx.x;
    const int lane = tid & 31;
    const int wid  = tid >> 5;

    if (blockIdx.x < TR_CTAS) {
        // ---------------- transpose branch (first: gather needs the table) --
        const int tb = blockIdx.x;
        const int f0 = (tb % TR_X) * 32;
        const int m0 = (tb / TR_X) * 32;
        {
            const int m = tid >> 3;
            const int q = tid & 7;
            const float4 v = *reinterpret_cast<const float4*>(
                ft_w + (size_t)(m0 + m) * NF + f0 + q * 4);
            tile[m][q * 4 + 0] = v.x;
            tile[m][q * 4 + 1] = v.y;
            tile[m][q * 4 + 2] = v.z;
            tile[m][q * 4 + 3] = v.w;
        }
        __syncthreads();
        {
            const int f  = tid >> 3;
            const int m4 = tid & 7;
            float4 v;
            v.x = tile[m4 * 4 + 0][f];
            v.y = tile[m4 * 4 + 1][f];
            v.z = tile[m4 * 4 + 2][f];
            v.w = tile[m4 * 4 + 3][f];
            union { __half2 h[2]; uint2 u; } cv;
            cv.h[0] = __floats2half2_rn(v.x, v.y);
            cv.h[1] = __floats2half2_rn(v.z, v.w);
            *reinterpret_cast<uint2*>(
                g_ftwT + (size_t)(f0 + f) * MDIM + m0 + m4 * 4) = cv.u;
        }
        __syncthreads();
        if (tid == 0) {
            __threadfence();
            atomicAdd((unsigned long long*)&g_trdone, 1ULL);
        }
    } else if (blockIdx.x < TR_CTAS + SCAN_CTAS) {
        // ---------------- scan branch: one CTA per row, warp per eighth ----
        const int row    = blockIdx.x - TR_CTAS;
        const int eighth = wid;

        const float* rowp = (row < NB) ? (wf + (size_t)row * NF)
                                       : (bfeat + (size_t)(row - NB) * NF);
        const uint4* p = reinterpret_cast<const uint4*>(rowp) + eighth * CHUNK_V4;
        int* list = g_list + ((size_t)row * NSEG + eighth) * SEG_CAP;

        int base = 0;
        #pragma unroll
        for (int t = 0; t < 5; t++) {
            unsigned mask = 0u;
            #pragma unroll
            for (int g = 0; g < 2; g++) {
                uint4 v0 = __ldcs(&p[t * 256 + (g * 4 + 0) * 32 + lane]);
                uint4 v1 = __ldcs(&p[t * 256 + (g * 4 + 1) * 32 + lane]);
                uint4 v2 = __ldcs(&p[t * 256 + (g * 4 + 2) * 32 + lane]);
                uint4 v3 = __ldcs(&p[t * 256 + (g * 4 + 3) * 32 + lane]);
                const int s = g * 16;
                if (v0.x) mask |= 1u << (s + 0);  if (v0.y) mask |= 1u << (s + 1);
                if (v0.z) mask |= 1u << (s + 2);  if (v0.w) mask |= 1u << (s + 3);
                if (v1.x) mask |= 1u << (s + 4);  if (v1.y) mask |= 1u << (s + 5);
                if (v1.z) mask |= 1u << (s + 6);  if (v1.w) mask |= 1u << (s + 7);
                if (v2.x) mask |= 1u << (s + 8);  if (v2.y) mask |= 1u << (s + 9);
                if (v2.z) mask |= 1u << (s + 10); if (v2.w) mask |= 1u << (s + 11);
                if (v3.x) mask |= 1u << (s + 12); if (v3.y) mask |= 1u << (s + 13);
                if (v3.z) mask |= 1u << (s + 14); if (v3.w) mask |= 1u << (s + 15);
            }
            const unsigned bal = __ballot_sync(0xffffffffu, mask != 0u);
            if (bal) {
                const int c = __popc(mask);
                int inc = c;
                #pragma unroll
                for (int d = 1; d < 32; d <<= 1) {
                    const int n = __shfl_up_sync(0xffffffffu, inc, d);
                    if (lane >= d) inc += n;
                }
                const int exc   = inc - c;
                const int total = __shfl_sync(0xffffffffu, inc, 31);
                unsigned mm = mask;
                int k = 0;
                while (mm) {
                    const int bb = __ffs(mm) - 1;
                    mm &= mm - 1u;
                    const int f = eighth * 5120
                                + (t * 256 + (bb >> 2) * 32 + lane) * 4 + (bb & 3);
                    const int slot = base + exc + k;
                    if (slot < SEG_CAP) list[slot] = f;
                    k++;
                }
                base += total;
            }
        }
        if (lane == 0)
            g_scnt[row * NSEG + eighth] = (base < SEG_CAP) ? base : SEG_CAP;
        __syncthreads();
        if (tid == 0) {
            __threadfence();
            const int e = *(volatile int*)&g_epoch;
            atomicExch(&g_rowflag[row], e);
        }
    } else {
        // ---------------- gather branch: one CTA per position --------------
        const int b   = blockIdx.x - TR_CTAS - SCAN_CTAS;
        const int m4  = tid & 63;
        const int grp = tid >> 6;

        // stage l2_w while waiting is NOT safe (table may not be ready is
        // irrelevant for l2_w input — it's a harness input, always ready)
        #pragma unroll
        for (int i = tid; i < 1024; i += 256)
            s_l2w[(i >> 5) * 33 + (i & 31)] = l2_w[i];

        // dependency wait: table complete + both rows' lists ready
        if (tid == 0) {
            const int e = *(volatile int*)&g_epoch;
            const long long ttarget = (long long)e * TR_CTAS;
            while (*(volatile long long*)&g_trdone < ttarget) { }
            volatile int* rf = (volatile int*)g_rowflag;
            while (rf[b] < e) { }
            while (rf[NB + b] < e) { }
            __threadfence();
        }
        __syncthreads();

        // segment counts (L1-bypass: g_scnt lines are shared across rows)
        if (tid < 8)       s_cntW[tid]     = __ldcv(&g_scnt[b * NSEG + tid]);
        else if (tid < 16) s_cntB[tid - 8] = __ldcv(&g_scnt[(NB + b) * NSEG + (tid - 8)]);
        __syncthreads();

        // compact segments into dense lists (deterministic segment order)
        {
            const int seg  = tid >> 5;
            const int slot = tid & 31;
            const int cW = s_cntW[seg];
            const int cB = s_cntB[seg];
            int offW = 0, offB = 0;
            #pragma unroll
            for (int i = 0; i < 7; i++) {
                if (i < seg) { offW += s_cntW[i]; offB += s_cntB[i]; }
            }
            const int fW = g_list[((size_t)b * NSEG + seg) * SEG_CAP + slot];
            const int fB = g_list[((size_t)(NB + b) * NSEG + seg) * SEG_CAP + slot];
            __syncthreads();
            if (slot < cW) s_idxW[offW + slot] = fW;
            if (slot < cB) s_idxB[offB + slot] = fB;
            if (tid == 255) {
                s_nW = offW + cW;
                s_nB = offB + cB;
            }
        }
        __syncthreads();

        // fp16 gather (fp32 accumulate) over this thread's quarter
        {
            const int nW = s_nW;
            const int j0 = (nW * grp) >> 2;
            const int j1 = (nW * (grp + 1)) >> 2;
            float4 acc = make_float4(0.f, 0.f, 0.f, 0.f);
            int j = j0;
            for (; j + 4 <= j1; j += 4) {
                const float4 v0 = ld_row4h(s_idxW[j + 0], m4);
                const float4 v1 = ld_row4h(s_idxW[j + 1], m4);
                const float4 v2 = ld_row4h(s_idxW[j + 2], m4);
                const float4 v3 = ld_row4h(s_idxW[j + 3], m4);
                acc.x += v0.x; acc.y += v0.y; acc.z += v0.z; acc.w += v0.w;
                acc.x += v1.x; acc.y += v1.y; acc.z += v1.z; acc.w += v1.w;
                acc.x += v2.x; acc.y += v2.y; acc.z += v2.z; acc.w += v2.w;
                acc.x += v3.x; acc.y += v3.y; acc.z += v3.z; acc.w += v3.w;
            }
            for (; j < j1; j++) {
                const float4 v = ld_row4h(s_idxW[j], m4);
                acc.x += v.x; acc.y += v.y; acc.z += v.z; acc.w += v.w;
            }
            reinterpret_cast<float4*>(&s_pW[grp * 256])[m4] = acc;

            const int nB = s_nB;
            const int k0 = (nB * grp) >> 2;
            const int k1 = (nB * (grp + 1)) >> 2;
            acc = make_float4(0.f, 0.f, 0.f, 0.f);
            j = k0;
            for (; j + 4 <= k1; j += 4) {
                const float4 v0 = ld_row4h(s_idxB[j + 0], m4);
                const float4 v1 = ld_row4h(s_idxB[j + 1], m4);
                const float4 v2 = ld_row4h(s_idxB[j + 2], m4);
                const float4 v3 = ld_row4h(s_idxB[j + 3], m4);
                acc.x += v0.x; acc.y += v0.y; acc.z += v0.z; acc.w += v0.w;
                acc.x += v1.x; acc.y += v1.y; acc.z += v1.z; acc.w += v1.w;
                acc.x += v2.x; acc.y += v2.y; acc.z += v2.z; acc.w += v2.w;
                acc.x += v3.x; acc.y += v3.y; acc.z += v3.z; acc.w += v3.w;
            }
            for (; j < k1; j++) {
                const float4 v = ld_row4h(s_idxB[j], m4);
                acc.x += v.x; acc.y += v.y; acc.z += v.z; acc.w += v.w;
            }
            reinterpret_cast<float4*>(&s_pB[grp * 256])[m4] = acc;
        }
        __syncthreads();

        // combine quarters + bias + stm blend + clip
        {
            const float bias = ft_b[tid];
            const float accW = bias + s_pW[tid] + s_pW[256 + tid]
                                    + s_pW[512 + tid] + s_pW[768 + tid];
            const float accB = bias + s_pB[tid] + s_pB[256 + tid]
                                    + s_pB[512 + tid] + s_pB[768 + tid];
            const float s = stm[b];
            s_h[tid]       = clamp01(s * accW + (1.0f - s) * accB);
            s_h[256 + tid] = clamp01(s * accB + (1.0f - s) * accW);
        }
        __syncthreads();

        // L1: 512 -> 32, warp-per-output (4 outputs per warp)
        {
            const float4* hv = reinterpret_cast<const float4*>(s_h);
            #pragma unroll
            for (int r = 0; r < 4; r++) {
                const int n = wid * 4 + r;
                const float4* wr = reinterpret_cast<const float4*>(l1_w + n * 512);
                float p = 0.0f;
                #pragma unroll
                for (int i = 0; i < 4; i++) {
                    const float4 a = wr[i * 32 + lane];
                    const float4 x = hv[i * 32 + lane];
                    p += a.x * x.x;
                    p += a.y * x.y;
                    p += a.z * x.z;
                    p += a.w * x.w;
                }
                p += __shfl_down_sync(0xffffffffu, p, 16);
                p += __shfl_down_sync(0xffffffffu, p, 8);
                p += __shfl_down_sync(0xffffffffu, p, 4);
                p += __shfl_down_sync(0xffffffffu, p, 2);
                p += __shfl_down_sync(0xffffffffu, p, 1);
                if (lane == 0) s_l2x[n] = clamp01(p + l1_b[n]);
            }
        }
        __syncthreads();

        // L2 (32->32) from padded smem, L3 (32->1). Warp 0 only.
        if (tid < 32) {
            float q = l2_b[tid];
            #pragma unroll
            for (int k = 0; k < 32; k++) q += s_l2w[tid * 33 + k] * s_l2x[k];
            const float l3x = clamp01(q);
            float t = l3x * l3_w[tid];
            #pragma unroll
            for (int off = 16; off > 0; off >>= 1)
                t += __shfl_down_sync(0xffffffffu, t, off);
            if (tid == 0) {
                const float ev = clamp01(t + l3_b[0]);
                out[b] = (ev - 0.5f) * 2.0f * 10000.0f;
            }
        }
    }
}

// ---------------------------------------------------------------------------
// Launch
// ---------------------------------------------------------------------------
extern "C" void kernel_launch(void* const* d_in, const int* in_sizes, int n_in,
                              void* d_out, int out_size)
{
    const float* wf    = (const float*)d_in[0];
    const float* bfeat = (const float*)d_in[1];
    const float* stm   = (const float*)d_in[2];
    const float* ft_w  = (const float*)d_in[3];
    const float* ft_b  = (const float*)d_in[4];
    const float* l1_w  = (const float*)d_in[5];
    const float* l1_b  = (const float*)d_in[6];
    const float* l2_w  = (const float*)d_in[7];
    const float* l2_b  = (const float*)d_in[8];
    const float* l3_w  = (const float*)d_in[9];
    const float* l3_b  = (const float*)d_in[10];
    float* out = (float*)d_out;

    // 1) bump the dependency epoch (stream-ordered before the mega-kernel)
    bump_epoch_kernel<<<1, 32>>>();

    // 2) mega-kernel: transpose + scan + gather overlapped via row flags
    nnue_mega_kernel<<<TOTAL_CTAS, 256>>>(wf, bfeat, ft_w, stm, ft_b,
                                          l1_w, l1_b, l2_w, l2_b,
                                          l3_w, l3_b, out);
}

// round 16
// speedup vs baseline: 1.1910x; 1.1910x over previous
#include <cuda_runtime.h>
#include <cuda_fp16.h>
#include <cstdint>

#define NF       40960
#define MDIM     256
#define NB       2048
#define ROWS     (2*NB)          // 4096 feature rows (white then black)
#define CHUNK_V4 1280            // float4s per warp chunk (NF/4/8)
#define NSEG     8               // segments per row (one per eighth)
#define SEG_CAP  32              // capacity per segment

#define SCAN_CTAS 4096           // 8 warps per CTA, warp per (row, eighth)
#define TR_X      (NF/32)        // 1280
#define TR_Y      (MDIM/32)      // 8
#define TR_CTAS   (TR_X*TR_Y)    // 10240

// fp16 transposed feature-transformer weights: ft_wT[f][m], 21 MB
__device__ __half g_ftwT[NF * MDIM];
// Per-(row, eighth) compact feature-index lists + counts (deterministic order)
__device__ int g_list[ROWS * NSEG * SEG_CAP];   // 4 MB
__device__ int g_scnt[ROWS * NSEG];

// ---------------------------------------------------------------------------
// Kernel 1: fused [streaming scan -> segment lists] + [ft_w transpose->fp16].
// (identical to the 121.3us round-14 version)
// ---------------------------------------------------------------------------
__global__ __launch_bounds__(256) void scan_transpose_kernel(
    const float* __restrict__ wf,
    const float* __restrict__ bfeat,
    const float* __restrict__ ft_w)
{
    __shared__ float tile[32][33];

    if (blockIdx.x < SCAN_CTAS) {
        const int gw     = (blockIdx.x << 3) | (threadIdx.x >> 5);
        const int lane   = threadIdx.x & 31;
        const int row    = gw >> 3;
        const int eighth = gw & 7;

        const float* rowp = (row < NB) ? (wf + (size_t)row * NF)
                                       : (bfeat + (size_t)(row - NB) * NF);
        const uint4* p = reinterpret_cast<const uint4*>(rowp) + eighth * CHUNK_V4;
        int* list = g_list + ((size_t)row * NSEG + eighth) * SEG_CAP;

        int base = 0;   // warp-uniform count so far

        #pragma unroll
        for (int t = 0; t < 5; t++) {
            unsigned mask = 0u;
            #pragma unroll
            for (int g = 0; g < 2; g++) {
                uint4 v0 = __ldcs(&p[t * 256 + (g * 4 + 0) * 32 + lane]);
                uint4 v1 = __ldcs(&p[t * 256 + (g * 4 + 1) * 32 + lane]);
                uint4 v2 = __ldcs(&p[t * 256 + (g * 4 + 2) * 32 + lane]);
                uint4 v3 = __ldcs(&p[t * 256 + (g * 4 + 3) * 32 + lane]);
                const int s = g * 16;
                if (v0.x) mask |= 1u << (s + 0);  if (v0.y) mask |= 1u << (s + 1);
                if (v0.z) mask |= 1u << (s + 2);  if (v0.w) mask |= 1u << (s + 3);
                if (v1.x) mask |= 1u << (s + 4);  if (v1.y) mask |= 1u << (s + 5);
                if (v1.z) mask |= 1u << (s + 6);  if (v1.w) mask |= 1u << (s + 7);
                if (v2.x) mask |= 1u << (s + 8);  if (v2.y) mask |= 1u << (s + 9);
                if (v2.z) mask |= 1u << (s + 10); if (v2.w) mask |= 1u << (s + 11);
                if (v3.x) mask |= 1u << (s + 12); if (v3.y) mask |= 1u << (s + 13);
                if (v3.z) mask |= 1u << (s + 14); if (v3.w) mask |= 1u << (s + 15);
            }

            const unsigned bal = __ballot_sync(0xffffffffu, mask != 0u);
            if (bal) {
                const int c = __popc(mask);
                int inc = c;
                #pragma unroll
                for (int d = 1; d < 32; d <<= 1) {
                    const int n = __shfl_up_sync(0xffffffffu, inc, d);
                    if (lane >= d) inc += n;
                }
                const int exc   = inc - c;
                const int total = __shfl_sync(0xffffffffu, inc, 31);
                unsigned mm = mask;
                int k = 0;
                while (mm) {
                    const int bb = __ffs(mm) - 1;
                    mm &= mm - 1u;
                    const int f = eighth * 5120
                                + (t * 256 + (bb >> 2) * 32 + lane) * 4 + (bb & 3);
                    const int slot = base + exc + k;
                    if (slot < SEG_CAP) list[slot] = f;
                    k++;
                }
                base += total;
            }
        }
        if (lane == 0)
            g_scnt[row * NSEG + eighth] = (base < SEG_CAP) ? base : SEG_CAP;
    } else {
        const int tb = blockIdx.x - SCAN_CTAS;
        const int f0 = (tb % TR_X) * 32;
        const int m0 = (tb / TR_X) * 32;
        const int t  = threadIdx.x;
        {
            const int m = t >> 3;
            const int q = t & 7;
            const float4 v = *reinterpret_cast<const float4*>(
                ft_w + (size_t)(m0 + m) * NF + f0 + q * 4);
            tile[m][q * 4 + 0] = v.x;
            tile[m][q * 4 + 1] = v.y;
            tile[m][q * 4 + 2] = v.z;
            tile[m][q * 4 + 3] = v.w;
        }
        __syncthreads();
        {
            const int f  = t >> 3;
            const int m4 = t & 7;
            float4 v;
            v.x = tile[m4 * 4 + 0][f];
            v.y = tile[m4 * 4 + 1][f];
            v.z = tile[m4 * 4 + 2][f];
            v.w = tile[m4 * 4 + 3][f];
            union { __half2 h[2]; uint2 u; } cv;
            cv.h[0] = __floats2half2_rn(v.x, v.y);
            cv.h[1] = __floats2half2_rn(v.z, v.w);
            *reinterpret_cast<uint2*>(
                g_ftwT + (size_t)(f0 + f) * MDIM + m0 + m4 * 4) = cv.u;
        }
    }
}

// ---------------------------------------------------------------------------
// Kernel 2: compaction + fp16 gather (W/B chains INTERLEAVED for 2x MLP
// against DRAM first-touch latency) + MLP tail. 256 threads/position.
// ---------------------------------------------------------------------------
__device__ __forceinline__ float clamp01(float x) {
    return fminf(fmaxf(x, 0.0f), 1.0f);
}

__device__ __forceinline__ float4 ld_row4h(int f, int m4) {
    const uint2 u = reinterpret_cast<const uint2*>(g_ftwT + (size_t)f * MDIM)[m4];
    const __half2 h0 = *reinterpret_cast<const __half2*>(&u.x);
    const __half2 h1 = *reinterpret_cast<const __half2*>(&u.y);
    const float2 f0 = __half22float2(h0);
    const float2 f1 = __half22float2(h1);
    return make_float4(f0.x, f0.y, f1.x, f1.y);
}

__global__ __launch_bounds__(256) void gather_mlp_kernel(
    const float* __restrict__ stm,
    const float* __restrict__ ft_b,
    const float* __restrict__ l1_w,
    const float* __restrict__ l1_b,
    const float* __restrict__ l2_w,
    const float* __restrict__ l2_b,
    const float* __restrict__ l3_w,
    const float* __restrict__ l3_b,
    float* __restrict__ out)
{
    const int b    = blockIdx.x;
    const int tid  = threadIdx.x;
    const int lane = tid & 31;
    const int wid  = tid >> 5;
    const int m4   = tid & 63;     // half2x2 column group (m = m4*4..m4*4+3)
    const int grp  = tid >> 6;     // quarter of the index list

    __shared__ __align__(16) float s_h[512];
    __shared__ __align__(16) float s_pW[4 * 256];
    __shared__ __align__(16) float s_pB[4 * 256];
    __shared__ __align__(16) int   s_idxW[NSEG * SEG_CAP];  // 256
    __shared__ __align__(16) int   s_idxB[NSEG * SEG_CAP];
    __shared__ float s_l2w[32 * 33];
    __shared__ float s_l2x[32];
    __shared__ int   s_cntW[8], s_cntB[8];
    __shared__ int   s_nW, s_nB;

    // issue dependent-path loads FIRST (counts), then staging
    if (tid < 8)       s_cntW[tid]     = __ldcv(&g_scnt[b * NSEG + tid]);
    else if (tid < 16) s_cntB[tid - 8] = __ldcv(&g_scnt[(NB + b) * NSEG + (tid - 8)]);

    // stage l2_w into padded smem (independent; overlaps the count latency)
    #pragma unroll
    for (int i = tid; i < 1024; i += 256)
        s_l2w[(i >> 5) * 33 + (i & 31)] = l2_w[i];
    __syncthreads();

    // compact the 8 segments into dense lists (deterministic segment order)
    {
        const int seg  = tid >> 5;
        const int slot = tid & 31;
        const int cW = s_cntW[seg];
        const int cB = s_cntB[seg];
        int offW = 0, offB = 0;
        #pragma unroll
        for (int i = 0; i < 7; i++) {
            if (i < seg) { offW += s_cntW[i]; offB += s_cntB[i]; }
        }
        const int fW = g_list[((size_t)b * NSEG + seg) * SEG_CAP + slot];
        const int fB = g_list[((size_t)(NB + b) * NSEG + seg) * SEG_CAP + slot];
        __syncthreads();
        if (slot < cW) s_idxW[offW + slot] = fW;
        if (slot < cB) s_idxB[offB + slot] = fB;
        if (tid == 255) {
            s_nW = offW + cW;
            s_nB = offB + cB;
        }
    }
    __syncthreads();

    // ---- fp16 gather, W and B chains interleaved (8 loads in flight) ----
    {
        const int nW  = s_nW;
        const int nB  = s_nB;
        const int j1W = (nW * (grp + 1)) >> 2;
        const int j1B = (nB * (grp + 1)) >> 2;
        int jw = (nW * grp) >> 2;
        int jb = (nB * grp) >> 2;

        float4 aW = make_float4(0.f, 0.f, 0.f, 0.f);
        float4 aB = make_float4(0.f, 0.f, 0.f, 0.f);

        // interleaved main loop: 4 W + 4 B independent loads per round
        while (jw + 4 <= j1W && jb + 4 <= j1B) {
            const float4 w0 = ld_row4h(s_idxW[jw + 0], m4);
            const float4 w1 = ld_row4h(s_idxW[jw + 1], m4);
            const float4 w2 = ld_row4h(s_idxW[jw + 2], m4);
            const float4 w3 = ld_row4h(s_idxW[jw + 3], m4);
            const float4 b0 = ld_row4h(s_idxB[jb + 0], m4);
            const float4 b1 = ld_row4h(s_idxB[jb + 1], m4);
            const float4 b2 = ld_row4h(s_idxB[jb + 2], m4);
            const float4 b3 = ld_row4h(s_idxB[jb + 3], m4);
            aW.x += w0.x; aW.y += w0.y; aW.z += w0.z; aW.w += w0.w;
            aW.x += w1.x; aW.y += w1.y; aW.z += w1.z; aW.w += w1.w;
            aW.x += w2.x; aW.y += w2.y; aW.z += w2.z; aW.w += w2.w;
            aW.x += w3.x; aW.y += w3.y; aW.z += w3.z; aW.w += w3.w;
            aB.x += b0.x; aB.y += b0.y; aB.z += b0.z; aB.w += b0.w;
            aB.x += b1.x; aB.y += b1.y; aB.z += b1.z; aB.w += b1.w;
            aB.x += b2.x; aB.y += b2.y; aB.z += b2.z; aB.w += b2.w;
            aB.x += b3.x; aB.y += b3.y; aB.z += b3.z; aB.w += b3.w;
            jw += 4; jb += 4;
        }
        // W remainder (4-wide then singles)
        while (jw + 4 <= j1W) {
            const float4 w0 = ld_row4h(s_idxW[jw + 0], m4);
            const float4 w1 = ld_row4h(s_idxW[jw + 1], m4);
            const float4 w2 = ld_row4h(s_idxW[jw + 2], m4);
            const float4 w3 = ld_row4h(s_idxW[jw + 3], m4);
            aW.x += w0.x; aW.y += w0.y; aW.z += w0.z; aW.w += w0.w;
            aW.x += w1.x; aW.y += w1.y; aW.z += w1.z; aW.w += w1.w;
            aW.x += w2.x; aW.y += w2.y; aW.z += w2.z; aW.w += w2.w;
            aW.x += w3.x; aW.y += w3.y; aW.z += w3.z; aW.w += w3.w;
            jw += 4;
        }
        for (; jw < j1W; jw++) {
            const float4 v = ld_row4h(s_idxW[jw], m4);
            aW.x += v.x; aW.y += v.y; aW.z += v.z; aW.w += v.w;
        }
        // B remainder
        while (jb + 4 <= j1B) {
            const float4 b0 = ld_row4h(s_idxB[jb + 0], m4);
            const float4 b1 = ld_row4h(s_idxB[jb + 1], m4);
            const float4 b2 = ld_row4h(s_idxB[jb + 2], m4);
            const float4 b3 = ld_row4h(s_idxB[jb + 3], m4);
            aB.x += b0.x; aB.y += b0.y; aB.z += b0.z; aB.w += b0.w;
            aB.x += b1.x; aB.y += b1.y; aB.z += b1.z; aB.w += b1.w;
            aB.x += b2.x; aB.y += b2.y; aB.z += b2.z; aB.w += b2.w;
            aB.x += b3.x; aB.y += b3.y; aB.z += b3.z; aB.w += b3.w;
            jb += 4;
        }
        for (; jb < j1B; jb++) {
            const float4 v = ld_row4h(s_idxB[jb], m4);
            aB.x += v.x; aB.y += v.y; aB.z += v.z; aB.w += v.w;
        }

        reinterpret_cast<float4*>(&s_pW[grp * 256])[m4] = aW;
        reinterpret_cast<float4*>(&s_pB[grp * 256])[m4] = aB;
    }
    __syncthreads();

    // ---- combine quarters (fixed g-order) + bias + stm blend + clip ----
    {
        const float bias = ft_b[tid];
        const float accW = bias + s_pW[tid] + s_pW[256 + tid]
                                + s_pW[512 + tid] + s_pW[768 + tid];
        const float accB = bias + s_pB[tid] + s_pB[256 + tid]
                                + s_pB[512 + tid] + s_pB[768 + tid];
        const float s = stm[b];
        s_h[tid]       = clamp01(s * accW + (1.0f - s) * accB);
        s_h[256 + tid] = clamp01(s * accB + (1.0f - s) * accW);
    }
    __syncthreads();

    // L1: 512 -> 32, warp-per-output (4 outputs per warp), coalesced rows.
    {
        const float4* hv = reinterpret_cast<const float4*>(s_h);
        #pragma unroll
        for (int r = 0; r < 4; r++) {
            const int n = wid * 4 + r;
            const float4* wr = reinterpret_cast<const float4*>(l1_w + n * 512);
            float p = 0.0f;
            #pragma unroll
            for (int i = 0; i < 4; i++) {
                const float4 a = wr[i * 32 + lane];
                const float4 x = hv[i * 32 + lane];
                p += a.x * x.x;
                p += a.y * x.y;
                p += a.z * x.z;
                p += a.w * x.w;
            }
            p += __shfl_down_sync(0xffffffffu, p, 16);
            p += __shfl_down_sync(0xffffffffu, p, 8);
            p += __shfl_down_sync(0xffffffffu, p, 4);
            p += __shfl_down_sync(0xffffffffu, p, 2);
            p += __shfl_down_sync(0xffffffffu, p, 1);
            if (lane == 0) s_l2x[n] = clamp01(p + l1_b[n]);
        }
    }
    __syncthreads();

    // L2 (32->32) from padded smem, L3 (32->1). Warp 0 only.
    if (tid < 32) {
        float q = l2_b[tid];
        #pragma unroll
        for (int k = 0; k < 32; k++) q += s_l2w[tid * 33 + k] * s_l2x[k];
        const float l3x = clamp01(q);
        float t = l3x * l3_w[tid];
        #pragma unroll
        for (int off = 16; off > 0; off >>= 1)
            t += __shfl_down_sync(0xffffffffu, t, off);
        if (tid == 0) {
            const float ev = clamp01(t + l3_b[0]);
            out[b] = (ev - 0.5f) * 2.0f * 10000.0f;
        }
    }
}

// ---------------------------------------------------------------------------
// Launch
// ---------------------------------------------------------------------------
extern "C" void kernel_launch(void* const* d_in, const int* in_sizes, int n_in,
                              void* d_out, int out_size)
{
    const float* wf    = (const float*)d_in[0];
    const float* bfeat = (const float*)d_in[1];
    const float* stm   = (const float*)d_in[2];
    const float* ft_w  = (const float*)d_in[3];
    const float* ft_b  = (const float*)d_in[4];
    const float* l1_w  = (const float*)d_in[5];
    const float* l1_b  = (const float*)d_in[6];
    const float* l2_w  = (const float*)d_in[7];
    const float* l2_b  = (const float*)d_in[8];
    const float* l3_w  = (const float*)d_in[9];
    const float* l3_b  = (const float*)d_in[10];
    float* out = (float*)d_out;

    // 1) Fused scan (segment lists) + fp16 transpose in one grid
    scan_transpose_kernel<<<SCAN_CTAS + TR_CTAS, 256>>>(wf, bfeat, ft_w);

    // 2) Compaction + interleaved fp16 gather + MLP tail, one CTA per position
    gather_mlp_kernel<<<NB, 256>>>(stm, ft_b, l1_w, l1_b, l2_w, l2_b,
                                   l3_w, l3_b, out);
}